// round 13
// baseline (speedup 1.0000x reference)
#include <cuda_runtime.h>
#include <math.h>

// Problem constants
#define BATCH 64
#define NSEQ  256
#define MSEQ  256
#define DDIM  512
#define BIGF  1e8f

// Scratch (device globals — no runtime allocation allowed)
// Z: [hx;hy] @ [Wm|Wg] + [bm|bg]  -> 32768 rows x 1024 cols
__device__ float g_Z[32768u * 1024u];
// Per-cell backward log-weights (u-L, w-L), diag-major: 513 diagonals x 257
__device__ float2 g_W[(size_t)BATCH * 513 * 257];

// ---- packed-fp32 helpers (fma.rn.f32x2) ----
__device__ __forceinline__ unsigned long long pk2(float lo, float hi) {
    unsigned long long r;
    asm("mov.b64 %0, {%1, %2};" : "=l"(r) : "f"(lo), "f"(hi));
    return r;
}
__device__ __forceinline__ void upk2(unsigned long long v, float& lo, float& hi) {
    asm("mov.b64 {%0, %1}, %2;" : "=f"(lo), "=f"(hi) : "l"(v));
}
__device__ __forceinline__ unsigned long long ffma2(unsigned long long a,
        unsigned long long b, unsigned long long c) {
    unsigned long long d;
    asm("fma.rn.f32x2 %0, %1, %2, %3;" : "=l"(d) : "l"(a), "l"(b), "l"(c));
    return d;
}

// ---------------------------------------------------------------------------
// K1: projection GEMM.  Z[r, 0:512]   = X[r] @ Wm + bm
//                       Z[r, 512:1024]= X[r] @ Wg + bg
// 128x128x8 tile, 256 threads, 8x8/thread, double-buffered smem, f32x2 FMA.
// (R11 configuration — best measured: 879us.)
// ---------------------------------------------------------------------------
__global__ __launch_bounds__(256) void k_proj(
    const float* __restrict__ hx, const float* __restrict__ hy,
    const float* __restrict__ Wm, const float* __restrict__ bm,
    const float* __restrict__ Wg, const float* __restrict__ bg)
{
    __shared__ float As[2][8][128];
    __shared__ float Bs[2][8][128];

    const int tid = threadIdx.x;
    const int bx  = blockIdx.x;      // 0..7 : output-column tiles of 128
    const int by  = blockIdx.y;      // 0..255 : row tiles of 128
    const int row0 = by * 128;

    const float* X    = (row0 < 16384) ? (hx + (size_t)row0 * 512)
                                       : (hy + (size_t)(row0 - 16384) * 512);
    const float* W    = (bx < 4) ? Wm : Wg;
    const float* bias = (bx < 4) ? bm : bg;
    const int wc0     = (bx < 4) ? bx * 128 : (bx - 4) * 128;

    const int a_row = tid >> 1;          // 0..127
    const int a_col = (tid & 1) * 4;     // 0 or 4
    const int b_row = tid >> 5;          // 0..7
    const int b_col = (tid & 31) * 4;    // 0..124

    const int ty = tid >> 4;             // 0..15
    const int tx = tid & 15;             // 0..15

    unsigned long long acc2[8][4];       // 8 rows x 4 col-pairs of f32x2
#pragma unroll
    for (int i = 0; i < 8; i++)
#pragma unroll
        for (int p = 0; p < 4; p++) acc2[i][p] = 0ull;

    // preload stage 0
    float4 av = *(const float4*)(X + (size_t)a_row * 512 + a_col);
    float4 bv = *(const float4*)(W + (size_t)b_row * 512 + wc0 + b_col);
    As[0][a_col + 0][a_row] = av.x;
    As[0][a_col + 1][a_row] = av.y;
    As[0][a_col + 2][a_row] = av.z;
    As[0][a_col + 3][a_row] = av.w;
    *(float4*)&Bs[0][b_row][b_col] = bv;
    __syncthreads();

    int s = 0;
    for (int k0 = 0; k0 < 512; k0 += 8) {
        if (k0 + 8 < 512) {
            av = *(const float4*)(X + (size_t)a_row * 512 + (k0 + 8) + a_col);
            bv = *(const float4*)(W + (size_t)(k0 + 8 + b_row) * 512 + wc0 + b_col);
        }
#pragma unroll
        for (int kk = 0; kk < 8; kk++) {
            const float4* ap = (const float4*)&As[s][kk][ty * 8];
            float4 a0 = ap[0], a1 = ap[1];
            const float4* bp = (const float4*)&Bs[s][kk][tx * 8];
            float4 b0 = bp[0], b1 = bp[1];
            unsigned long long bb0 = pk2(b0.x, b0.y), bb1 = pk2(b0.z, b0.w);
            unsigned long long bb2 = pk2(b1.x, b1.y), bb3 = pk2(b1.z, b1.w);
            float ar[8] = {a0.x, a0.y, a0.z, a0.w, a1.x, a1.y, a1.z, a1.w};
#pragma unroll
            for (int i = 0; i < 8; i++) {
                unsigned long long aa = pk2(ar[i], ar[i]);
                acc2[i][0] = ffma2(aa, bb0, acc2[i][0]);
                acc2[i][1] = ffma2(aa, bb1, acc2[i][1]);
                acc2[i][2] = ffma2(aa, bb2, acc2[i][2]);
                acc2[i][3] = ffma2(aa, bb3, acc2[i][3]);
            }
        }
        if (k0 + 8 < 512) {
            As[s ^ 1][a_col + 0][a_row] = av.x;
            As[s ^ 1][a_col + 1][a_row] = av.y;
            As[s ^ 1][a_col + 2][a_row] = av.z;
            As[s ^ 1][a_col + 3][a_row] = av.w;
            *(float4*)&Bs[s ^ 1][b_row][b_col] = bv;
            __syncthreads();
            s ^= 1;
        }
    }

#pragma unroll
    for (int i = 0; i < 8; i++) {
        const int row = row0 + ty * 8 + i;
#pragma unroll
        for (int p = 0; p < 4; p++) {
            float lo, hi;
            upk2(acc2[i][p], lo, hi);
            const int c = tx * 8 + 2 * p;
            g_Z[(size_t)row * 1024 + bx * 128 + c]     = lo + bias[wc0 + c];
            g_Z[(size_t)row * 1024 + bx * 128 + c + 1] = hi + bias[wc0 + c + 1];
        }
    }
}

// ---------------------------------------------------------------------------
// K2: per-batch NT GEMM + activation (R11 configuration).
//  which==0: theta[b] = softplus(zx[b] @ zy[b]^T)
//  which==1: A[b]     = log_sigmoid(gx[b] @ gy[b]^T)
// ---------------------------------------------------------------------------
__global__ __launch_bounds__(256) void k_pair(float* __restrict__ theta,
                                              float* __restrict__ Aout)
{
    __shared__ float As[2][8][128];
    __shared__ float Bs[2][8][128];

    const int tid   = threadIdx.x;
    const int bz    = blockIdx.z;
    const int batch = bz >> 1;
    const int which = bz & 1;
    const int ro    = blockIdx.y * 128;
    const int co    = blockIdx.x * 128;

    const float* Xb = g_Z + (size_t)(batch * 256) * 1024 + (which ? 512 : 0);
    const float* Yb = g_Z + (size_t)(16384 + batch * 256) * 1024 + (which ? 512 : 0);

    const int a_row = tid >> 1;
    const int a_col = (tid & 1) * 4;
    const int ty = tid >> 4;
    const int tx = tid & 15;

    unsigned long long acc2[8][4];
#pragma unroll
    for (int i = 0; i < 8; i++)
#pragma unroll
        for (int p = 0; p < 4; p++) acc2[i][p] = 0ull;

    float4 av = *(const float4*)(Xb + (size_t)(ro + a_row) * 1024 + a_col);
    float4 bv = *(const float4*)(Yb + (size_t)(co + a_row) * 1024 + a_col);
    As[0][a_col + 0][a_row] = av.x;
    As[0][a_col + 1][a_row] = av.y;
    As[0][a_col + 2][a_row] = av.z;
    As[0][a_col + 3][a_row] = av.w;
    Bs[0][a_col + 0][a_row] = bv.x;
    Bs[0][a_col + 1][a_row] = bv.y;
    Bs[0][a_col + 2][a_row] = bv.z;
    Bs[0][a_col + 3][a_row] = bv.w;
    __syncthreads();

    int s = 0;
    for (int k0 = 0; k0 < 512; k0 += 8) {
        if (k0 + 8 < 512) {
            av = *(const float4*)(Xb + (size_t)(ro + a_row) * 1024 + (k0 + 8) + a_col);
            bv = *(const float4*)(Yb + (size_t)(co + a_row) * 1024 + (k0 + 8) + a_col);
        }
#pragma unroll
        for (int kk = 0; kk < 8; kk++) {
            const float4* ap = (const float4*)&As[s][kk][ty * 8];
            float4 a0 = ap[0], a1 = ap[1];
            const float4* bp = (const float4*)&Bs[s][kk][tx * 8];
            float4 b0 = bp[0], b1 = bp[1];
            unsigned long long bb0 = pk2(b0.x, b0.y), bb1 = pk2(b0.z, b0.w);
            unsigned long long bb2 = pk2(b1.x, b1.y), bb3 = pk2(b1.z, b1.w);
            float ar[8] = {a0.x, a0.y, a0.z, a0.w, a1.x, a1.y, a1.z, a1.w};
#pragma unroll
            for (int i = 0; i < 8; i++) {
                unsigned long long aa = pk2(ar[i], ar[i]);
                acc2[i][0] = ffma2(aa, bb0, acc2[i][0]);
                acc2[i][1] = ffma2(aa, bb1, acc2[i][1]);
                acc2[i][2] = ffma2(aa, bb2, acc2[i][2]);
                acc2[i][3] = ffma2(aa, bb3, acc2[i][3]);
            }
        }
        if (k0 + 8 < 512) {
            As[s ^ 1][a_col + 0][a_row] = av.x;
            As[s ^ 1][a_col + 1][a_row] = av.y;
            As[s ^ 1][a_col + 2][a_row] = av.z;
            As[s ^ 1][a_col + 3][a_row] = av.w;
            Bs[s ^ 1][a_col + 0][a_row] = bv.x;
            Bs[s ^ 1][a_col + 1][a_row] = bv.y;
            Bs[s ^ 1][a_col + 2][a_row] = bv.z;
            Bs[s ^ 1][a_col + 3][a_row] = bv.w;
            __syncthreads();
            s ^= 1;
        }
    }

    float* O = which ? Aout : theta;
    const size_t base = (size_t)batch * NSEQ * MSEQ;
#pragma unroll
    for (int i = 0; i < 8; i++) {
        const int row = ro + ty * 8 + i;
#pragma unroll
        for (int p = 0; p < 4; p++) {
            float xv[2];
            upk2(acc2[i][p], xv[0], xv[1]);
#pragma unroll
            for (int h = 0; h < 2; h++) {
                float x  = xv[h];
                float l1 = log1pf(expf(-fabsf(x)));
                float v  = which ? (fminf(x, 0.f) - l1)    // log_sigmoid
                                 : (fmaxf(x, 0.f) + l1);   // softplus
                O[base + (size_t)row * MSEQ + (co + tx * 8 + 2 * p + h)] = v;
            }
        }
    }
}

// float4 component select without local-array spill
__device__ __forceinline__ float f4sel(const float4& v, int sel) {
    float lo = (sel == 0) ? v.x : v.y;
    float hi = (sel == 2) ? v.z : v.w;
    return (sel < 2) ? lo : hi;
}

// ---------------------------------------------------------------------------
// K3: smooth NW forward + backward, one block/batch, all-float difference
// recurrence. Forward unchanged from R11/R12 (passing, 7.5e-5).
// Backward rewritten in GATHER form — ONE __syncthreads per step (was two):
//   E_k(i) = PU_{k+1}[i+1] + PL_{k+1}[i] + PD_{k+2}[i+1]
// where cell (diag k, slot i) publishes pu=E*exp(u-L), pl=E*exp(w-L),
// pd=E-pu-pl into ring buffers (PU/PL depth 2, PD depth 3). Reads hit slots
// written 1-2 steps ago (distinct ring slots from this step's writes), so a
// single barrier orders everything. E-accumulator arrays + clear pass gone.
// ---------------------------------------------------------------------------
__global__ __launch_bounds__(256) void k_nw(const float* __restrict__ theta,
                                            const float* __restrict__ Aarr,
                                            float* __restrict__ aln)
{
    const int b = blockIdx.x;
    const int t = threadIdx.x;
    const float* TH = theta + (size_t)b * NSEQ * MSEQ;
    const float* AA = Aarr  + (size_t)b * NSEQ * MSEQ;
    float*       AL = aln   + (size_t)b * NSEQ * MSEQ;
    float2*      Wd = g_W   + (size_t)b * 513 * 257;

    __shared__ float Rb[2][258], Cb[2][258];          // forward diff diagonals
    __shared__ float PU[2][258], PL[2][258], PD[3][258];  // backward rings

    const int i = t + 1;   // matrix row index 1..256
    const float* rowT = TH + (size_t)(i - 1) * MSEQ;
    const float* rowA = AA + (size_t)(i - 1) * MSEQ;
    float*       rowL = AL + (size_t)(i - 1) * MSEQ;

    // -------- forward --------
    for (int m = t; m < 258; m += 256) {
        Rb[0][m] = 0.f; Cb[0][m] = 0.f;
    }
    if (t == 0) { Rb[0][0] = -BIGF; Cb[0][1] = -BIGF; }  // R(0,1), C(1,0)
    float4 tC, tN, aC, aN;
    tN = *(const float4*)rowT;            // chunk 0 prefetch
    aN = *(const float4*)rowA;
    __syncthreads();

    int s = 0;
    for (int k = 2; k <= 512; k++) {
        const int jm1 = k - i - 1;        // 0-based column this thread touches
        if (jm1 >= 0 && jm1 < MSEQ) {
            const int sel = jm1 & 3;
            if (sel == 0) {
                tC = tN; aC = aN;
                if (jm1 + 4 < MSEQ) {
                    tN = *(const float4*)(rowT + jm1 + 4);
                    aN = *(const float4*)(rowA + jm1 + 4);
                }
            }
            float th = f4sel(tC, sel);
            float a  = f4sel(aC, sel);
            float u  = a + Rb[s][i - 1];                // c0 - c1
            float w  = a + Cb[s][i];                    // c2 - c1
            float m1 = fmaxf(fmaxf(u, w), 0.f);
            float L  = m1 + __logf(__expf(u - m1) + __expf(w - m1) +
                                   __expf(-m1));
            Rb[s ^ 1][i] = th + a + (L - w);
            Cb[s ^ 1][i] = th + a + (L - u);
            Wd[(size_t)k * 257 + i] = make_float2(u - L, w - L);
        }
        if (t == 0) Rb[s ^ 1][0] = 0.f;   // R(0,k), k>=2
        if (i == k) Cb[s ^ 1][i] = 0.f;   // C(k,0), k>=2 (k<=256 only)
        __syncthreads();
        s ^= 1;
    }

    // -------- backward (gather form, 1 sync/step) --------
    for (int m = t; m < 258; m += 256) {
        PU[0][m] = 0.f; PU[1][m] = 0.f;
        PL[0][m] = 0.f; PL[1][m] = 0.f;
        PD[0][m] = 0.f; PD[1][m] = 0.f; PD[2][m] = 0.f;
    }
    float4 alB = make_float4(0.f, 0.f, 0.f, 0.f);
    float2 cur = Wd[(size_t)512 * 257 + i];   // distance-2 prefetch pipeline
    float2 n1  = Wd[(size_t)511 * 257 + i];
    __syncthreads();

    int w3 = 512 % 3;                 // = 2 ; PD write slot for diag k
    int r3 = (512 + 2) % 3;           // = 1 ; PD read slot (diag k+2)
    for (int k = 512; k >= 2; k--) {
        float2 n2;
        if (k > 3) n2 = Wd[(size_t)(k - 2) * 257 + i];
        const int w2 = k & 1;         // PU/PL write slot (diag k)
        const int r2 = w2 ^ 1;        // PU/PL read slot  (diag k+1)
        const int jm1 = k - i - 1;

        float E = PU[r2][i + 1] + PL[r2][i] + PD[r3][i + 1];
        if (k == 512 && i == 256) E = 1.f;   // seed at (N, M)

        float pu = 0.f, pl = 0.f, pd = 0.f;
        if (jm1 >= 0 && jm1 < MSEQ) {
            pu = E * __expf(cur.x);   // weight toward parent (i-1, j)
            pl = E * __expf(cur.y);   // weight toward parent (i,   j-1)
            pd = E - pu - pl;         // weight toward parent (i-1, j-1)
            const int sel = jm1 & 3;
            if      (sel == 3) alB.w = E;
            else if (sel == 2) alB.z = E;
            else if (sel == 1) alB.y = E;
            else               alB.x = E;
            if (sel == 0) *(float4*)(rowL + jm1) = alB;   // chunk complete
        }
        PU[w2][i] = pu; PL[w2][i] = pl; PD[w3][i] = pd;
        __syncthreads();

        cur = n1; n1 = n2;
        w3 = (w3 == 0) ? 2 : w3 - 1;  // next k' = k-1: slot k'%3
        r3 = (r3 == 0) ? 2 : r3 - 1;
    }
}

// ---------------------------------------------------------------------------
// Launch. Inputs: hx, hy, Wm, bm, Wg, bg (f32).
// Output: concat(aln, theta, A), each (64,256,256) f32.
// ---------------------------------------------------------------------------
extern "C" void kernel_launch(void* const* d_in, const int* in_sizes, int n_in,
                              void* d_out, int out_size)
{
    const float* hx = (const float*)d_in[0];
    const float* hy = (const float*)d_in[1];
    const float* Wm = (const float*)d_in[2];
    const float* bm = (const float*)d_in[3];
    const float* Wg = (const float*)d_in[4];
    const float* bg = (const float*)d_in[5];

    float* out = (float*)d_out;
    size_t third = (size_t)out_size / 3;       // 64*256*256
    float* aln_p   = out;
    float* theta_p = out + third;
    float* A_p     = out + 2 * third;

    k_proj<<<dim3(8, 256), 256>>>(hx, hy, Wm, bm, Wg, bg);
    k_pair<<<dim3(2, 2, 2 * BATCH), 256>>>(theta_p, A_p);
    k_nw<<<BATCH, 256>>>(theta_p, A_p, aln_p);
}

// round 15
// speedup vs baseline: 1.6090x; 1.6090x over previous
#include <cuda_runtime.h>
#include <cuda_bf16.h>
#include <math.h>
#include <stdint.h>

// Problem constants
#define BATCH 64
#define NSEQ  256
#define MSEQ  256
#define BIGF  1e8f

// Scratch (device globals — no runtime allocation allowed)
__device__ float  g_Z [32768u * 1024u];        // [hx;hy] @ [Wm|Wg] + bias
__device__ float  g_Wt[1024u * 512u];          // W transposed: g_Wt[n][k]
__device__ float2 g_W [(size_t)BATCH * 513 * 257];  // NW backward log-weights

// ===========================================================================
// Helpers
// ===========================================================================
__device__ __forceinline__ uint32_t smem_u32(const void* p) {
    uint32_t a;
    asm("{ .reg .u64 t; cvta.to.shared.u64 t, %1; cvt.u32.u64 %0, t; }"
        : "=r"(a) : "l"(p));
    return a;
}
__device__ __forceinline__ void ldm_x4(uint32_t* r, uint32_t addr) {
    asm volatile("ldmatrix.sync.aligned.m8n8.x4.shared.b16 {%0,%1,%2,%3}, [%4];"
                 : "=r"(r[0]), "=r"(r[1]), "=r"(r[2]), "=r"(r[3]) : "r"(addr));
}
__device__ __forceinline__ void mma_bf16(float* c, const uint32_t* a,
                                         const uint32_t* b) {
    asm volatile(
        "mma.sync.aligned.m16n8k16.row.col.f32.bf16.bf16.f32 "
        "{%0,%1,%2,%3}, {%4,%5,%6,%7}, {%8,%9}, {%0,%1,%2,%3};"
        : "+f"(c[0]), "+f"(c[1]), "+f"(c[2]), "+f"(c[3])
        : "r"(a[0]), "r"(a[1]), "r"(a[2]), "r"(a[3]), "r"(b[0]), "r"(b[1]));
}
// bf16x3 split: x = hi + lo (hi = bf16 rn, lo = bf16 of residual)
__device__ __forceinline__ void split_pair(float x, float y,
                                           uint32_t& hi, uint32_t& lo) {
    __nv_bfloat16 hx = __float2bfloat16(x);
    __nv_bfloat16 hy = __float2bfloat16(y);
    __nv_bfloat162 h2; h2.x = hx; h2.y = hy;
    hi = *reinterpret_cast<uint32_t*>(&h2);
    __nv_bfloat162 l2;
    l2.x = __float2bfloat16(x - __bfloat162float(hx));
    l2.y = __float2bfloat16(y - __bfloat162float(hy));
    lo = *reinterpret_cast<uint32_t*>(&l2);
}

// ---------------------------------------------------------------------------
// K0: transpose W into g_Wt[n][k] (n<512: Wm col n; else Wg col n-512).
// ---------------------------------------------------------------------------
__global__ void k_wt(const float* __restrict__ Wm, const float* __restrict__ Wg)
{
    __shared__ float t[32][33];
    const int bx = blockIdx.x;            // k-tile 0..15
    const int by = blockIdx.y;            // n-tile 0..31
    const float* W = (by < 16) ? Wm : Wg;
    const int nb = (by < 16 ? by : by - 16) * 32;
    for (int r = threadIdx.y; r < 32; r += 8)
        t[r][threadIdx.x] = W[(size_t)(bx * 32 + r) * 512 + nb + threadIdx.x];
    __syncthreads();
    for (int r = threadIdx.y; r < 32; r += 8)
        g_Wt[(size_t)(by * 32 + r) * 512 + bx * 32 + threadIdx.x] =
            t[threadIdx.x][r];
}

// ---------------------------------------------------------------------------
// K1: bf16x3 split-mma GEMM (base-ISA mma.sync — compute_100-compatible).
// Block 128x128xK512; 8 warps in 4(m) x 2(n); warp tile 32x64 via m16n8k16.
// Smem tiles Ahi/Alo/Bhi/Blo: [128][32] bf16, 80B row stride (conflict-free
// for ldmatrix: 80 = 5*16B, 8-row phase hits banks {0,20,8,28,16,4,24,12}).
// B consumed [n][k] n-major == mma col-major B, so zy rows / g_Wt rows load
// directly. 3 products per tile: Ahi*Bhi + Ahi*Blo + Alo*Bhi (fp32 accum).
// mode 0 (proj): g_Z[row,n] = X @ g_Wt^T + bias
// mode 1 (pair): theta/A = act(zx @ zy^T)
// ---------------------------------------------------------------------------
__global__ __launch_bounds__(256) void k_mm(int mode,
    const float* __restrict__ hx, const float* __restrict__ hy,
    const float* __restrict__ bm, const float* __restrict__ bg,
    float* __restrict__ theta, float* __restrict__ Aout)
{
    __shared__ __align__(16) char sm[40960];
    const uint32_t sb = smem_u32(sm);
    const int tid = threadIdx.x, wid = tid >> 5, lane = tid & 31;

    const float *Asrc, *Bsrc, *bias = nullptr;
    size_t lda, ldb;
    int row0 = 0, n0 = 0, which = 0, batch = 0, mtile = 0, ntile = 0;
    if (mode == 0) {
        n0 = blockIdx.x * 128; row0 = blockIdx.y * 128;
        Asrc = (row0 < 16384) ? hx + (size_t)row0 * 512
                              : hy + (size_t)(row0 - 16384) * 512;
        lda = 512;
        Bsrc = g_Wt + (size_t)n0 * 512; ldb = 512;
        bias = (n0 < 512) ? bm + n0 : bg + (n0 - 512);
    } else {
        which = blockIdx.x >> 1; ntile = blockIdx.x & 1;
        batch = blockIdx.y >> 1; mtile = blockIdx.y & 1;
        Asrc = g_Z + (size_t)(batch * 256 + mtile * 128) * 1024 + which * 512;
        lda = 1024;
        Bsrc = g_Z + (size_t)(16384 + batch * 256 + ntile * 128) * 1024 + which * 512;
        ldb = 1024;
    }

    // smem tile offsets (each 128 rows x 80B = 10240B)
    const uint32_t AHo = 0, ALo = 10240, BHo = 20480, BLo = 30720;

    // gmem load coords: 2 threads per row, 16 cols each
    const int grow = tid >> 1;
    const int gc0  = (tid & 1) * 16;

    // ldmatrix per-lane smem addresses
    const int wm = wid >> 1, wn = wid & 1;
    const uint32_t aoff = (uint32_t)(lane & 15) * 80 + (uint32_t)(lane >> 4) * 16;
    const uint32_t boff =
        (uint32_t)((lane & 7) + ((lane >> 4) << 3)) * 80 +
        (uint32_t)((lane >> 3) & 1) * 16;
    const uint32_t a0h = sb + AHo + (uint32_t)(wm * 32) * 80 + aoff;
    const uint32_t a1h = a0h + 16 * 80;
    const uint32_t a0l = sb + ALo + (uint32_t)(wm * 32) * 80 + aoff;
    const uint32_t a1l = a0l + 16 * 80;
    uint32_t bph[4], bpl[4];
#pragma unroll
    for (int p = 0; p < 4; p++) {
        bph[p] = sb + BHo + (uint32_t)(wn * 64 + p * 16) * 80 + boff;
        bpl[p] = sb + BLo + (uint32_t)(wn * 64 + p * 16) * 80 + boff;
    }

    float c0[8][4], c1[8][4];
#pragma unroll
    for (int n = 0; n < 8; n++)
#pragma unroll
        for (int q = 0; q < 4; q++) { c0[n][q] = 0.f; c1[n][q] = 0.f; }

    // prefetch chunk 0
    float4 pa[4], pb[4];
#pragma unroll
    for (int q = 0; q < 4; q++) {
        pa[q] = *(const float4*)(Asrc + (size_t)grow * lda + gc0 + q * 4);
        pb[q] = *(const float4*)(Bsrc + (size_t)grow * ldb + gc0 + q * 4);
    }

    for (int k0 = 0; k0 < 512; k0 += 32) {
        // split + store current chunk to smem
#pragma unroll
        for (int q = 0; q < 4; q++) {
            uint32_t h0, l0, h1, l1;
            const uint32_t off = (uint32_t)grow * 80 + (uint32_t)gc0 * 2 + q * 8;
            split_pair(pa[q].x, pa[q].y, h0, l0);
            split_pair(pa[q].z, pa[q].w, h1, l1);
            *(uint2*)(sm + AHo + off) = make_uint2(h0, h1);
            *(uint2*)(sm + ALo + off) = make_uint2(l0, l1);
            split_pair(pb[q].x, pb[q].y, h0, l0);
            split_pair(pb[q].z, pb[q].w, h1, l1);
            *(uint2*)(sm + BHo + off) = make_uint2(h0, h1);
            *(uint2*)(sm + BLo + off) = make_uint2(l0, l1);
        }
        __syncthreads();
        // issue next chunk's gmem loads (overlap with mma phase)
        if (k0 + 32 < 512) {
#pragma unroll
            for (int q = 0; q < 4; q++) {
                pa[q] = *(const float4*)(Asrc + (size_t)grow * lda + (k0 + 32) + gc0 + q * 4);
                pb[q] = *(const float4*)(Bsrc + (size_t)grow * ldb + (k0 + 32) + gc0 + q * 4);
            }
        }
#pragma unroll
        for (int ks = 0; ks < 2; ks++) {
            const uint32_t ko = ks * 32;
            uint32_t AH0[4], AH1[4], AL0[4], AL1[4];
            ldm_x4(AH0, a0h + ko); ldm_x4(AH1, a1h + ko);
            ldm_x4(AL0, a0l + ko); ldm_x4(AL1, a1l + ko);
            uint32_t BHf[4][4], BLf[4][4];
#pragma unroll
            for (int p = 0; p < 4; p++) {
                ldm_x4(BHf[p], bph[p] + ko);
                ldm_x4(BLf[p], bpl[p] + ko);
            }
#pragma unroll
            for (int n = 0; n < 8; n++) {
                uint32_t* bh = &BHf[n >> 1][(n & 1) * 2];
                uint32_t* bl = &BLf[n >> 1][(n & 1) * 2];
                mma_bf16(c0[n], AH0, bh);
                mma_bf16(c0[n], AH0, bl);
                mma_bf16(c0[n], AL0, bh);
                mma_bf16(c1[n], AH1, bh);
                mma_bf16(c1[n], AH1, bl);
                mma_bf16(c1[n], AL1, bh);
            }
        }
        __syncthreads();
    }

    // epilogue: fragment (g = lane>>2 row, t = lane&3 col-pair)
    const int g  = lane >> 2;
    const int tt = (lane & 3) * 2;
#pragma unroll
    for (int mi = 0; mi < 2; mi++) {
        float (*cc)[4] = mi ? c1 : c0;
        const int rb = wm * 32 + mi * 16 + g;
#pragma unroll
        for (int n = 0; n < 8; n++) {
            const int col = wn * 64 + n * 8 + tt;
            if (mode == 0) {
                const int row = row0 + rb;
                const float b0v = bias[col], b1v = bias[col + 1];
                *(float2*)&g_Z[(size_t)row * 1024 + n0 + col] =
                    make_float2(cc[n][0] + b0v, cc[n][1] + b1v);
                *(float2*)&g_Z[(size_t)(row + 8) * 1024 + n0 + col] =
                    make_float2(cc[n][2] + b0v, cc[n][3] + b1v);
            } else {
                float* O = which ? Aout : theta;
                const int row  = mtile * 128 + rb;
                const int ocol = ntile * 128 + col;
                const size_t base = (size_t)batch * NSEQ * MSEQ;
                float v[4];
#pragma unroll
                for (int h = 0; h < 4; h++) {
                    float x  = cc[n][h];
                    float l1 = log1pf(expf(-fabsf(x)));
                    v[h] = which ? (fminf(x, 0.f) - l1)    // log_sigmoid
                                 : (fmaxf(x, 0.f) + l1);   // softplus
                }
                *(float2*)&O[base + (size_t)row * MSEQ + ocol] =
                    make_float2(v[0], v[1]);
                *(float2*)&O[base + (size_t)(row + 8) * MSEQ + ocol] =
                    make_float2(v[2], v[3]);
            }
        }
    }
}

// float4 component select without local-array spill
__device__ __forceinline__ float f4sel(const float4& v, int sel) {
    float lo = (sel == 0) ? v.x : v.y;
    float hi = (sel == 2) ? v.z : v.w;
    return (sel < 2) ? lo : hi;
}

// ---------------------------------------------------------------------------
// K3: smooth NW forward + backward (R12 configuration — best measured).
// All-float difference recurrence; scatter backward; dist-2 Wd prefetch.
// ---------------------------------------------------------------------------
__global__ __launch_bounds__(256) void k_nw(const float* __restrict__ theta,
                                            const float* __restrict__ Aarr,
                                            float* __restrict__ aln)
{
    const int b = blockIdx.x;
    const int t = threadIdx.x;
    const float* TH = theta + (size_t)b * NSEQ * MSEQ;
    const float* AA = Aarr  + (size_t)b * NSEQ * MSEQ;
    float*       AL = aln   + (size_t)b * NSEQ * MSEQ;
    float2*      Wd = g_W   + (size_t)b * 513 * 257;

    __shared__ float Rb[2][258], Cb[2][258];
    __shared__ float Eb_[258], E1_[258], E2_[258];
    __shared__ float cu[258], cl[258], cd[258];

    const int i = t + 1;
    const float* rowT = TH + (size_t)(i - 1) * MSEQ;
    const float* rowA = AA + (size_t)(i - 1) * MSEQ;
    float*       rowL = AL + (size_t)(i - 1) * MSEQ;

    // -------- forward --------
    for (int m = t; m < 258; m += 256) { Rb[0][m] = 0.f; Cb[0][m] = 0.f; }
    if (t == 0) { Rb[0][0] = -BIGF; Cb[0][1] = -BIGF; }
    float4 tC, tN, aC, aN;
    tN = *(const float4*)rowT;
    aN = *(const float4*)rowA;
    __syncthreads();

    int s = 0;
    for (int k = 2; k <= 512; k++) {
        const int jm1 = k - i - 1;
        if (jm1 >= 0 && jm1 < MSEQ) {
            const int sel = jm1 & 3;
            if (sel == 0) {
                tC = tN; aC = aN;
                if (jm1 + 4 < MSEQ) {
                    tN = *(const float4*)(rowT + jm1 + 4);
                    aN = *(const float4*)(rowA + jm1 + 4);
                }
            }
            float th = f4sel(tC, sel);
            float a  = f4sel(aC, sel);
            float u  = a + Rb[s][i - 1];
            float w  = a + Cb[s][i];
            float m1 = fmaxf(fmaxf(u, w), 0.f);
            float L  = m1 + __logf(__expf(u - m1) + __expf(w - m1) +
                                   __expf(-m1));
            Rb[s ^ 1][i] = th + a + (L - w);
            Cb[s ^ 1][i] = th + a + (L - u);
            Wd[(size_t)k * 257 + i] = make_float2(u - L, w - L);
        }
        if (t == 0) Rb[s ^ 1][0] = 0.f;
        if (i == k) Cb[s ^ 1][i] = 0.f;
        __syncthreads();
        s ^= 1;
    }

    // -------- backward (scatter, dist-2 prefetch) --------
    float *Eb = Eb_, *E1 = E1_, *E2 = E2_;
    for (int m = t; m < 258; m += 256) {
        Eb[m] = (m == 256) ? 1.f : 0.f;
        E1[m] = 0.f; E2[m] = 0.f;
        cu[m] = 0.f; cl[m] = 0.f; cd[m] = 0.f;
    }
    float4 alB = make_float4(0.f, 0.f, 0.f, 0.f);
    float2 cur = Wd[(size_t)512 * 257 + i];
    float2 n1  = Wd[(size_t)511 * 257 + i];
    __syncthreads();

    for (int k = 512; k >= 2; k--) {
        float2 n2;
        if (k > 3) n2 = Wd[(size_t)(k - 2) * 257 + i];
        const int jm1 = k - i - 1;
        float E = Eb[i];
        float wu = 0.f, wl = 0.f, wd = 0.f;
        if (jm1 >= 0 && jm1 < MSEQ) {
            wu = E * __expf(cur.x);
            wl = E * __expf(cur.y);
            wd = E - wu - wl;
            const int sel = jm1 & 3;
            if      (sel == 3) alB.w = E;
            else if (sel == 2) alB.z = E;
            else if (sel == 1) alB.y = E;
            else               alB.x = E;
            if (sel == 0) *(float4*)(rowL + jm1) = alB;
        }
        cu[i] = wu; cl[i] = wl; cd[i] = wd;
        __syncthreads();

        for (int m = t; m < 257; m += 256) {
            E1[m] += cu[m + 1] + cl[m];
            E2[m] += cd[m + 1];
        }
        for (int m = t; m < 258; m += 256) Eb[m] = 0.f;
        __syncthreads();

        float* tE = Eb; Eb = E1; E1 = E2; E2 = tE;
        cur = n1; n1 = n2;
    }
}

// ---------------------------------------------------------------------------
// Launch. Inputs: hx, hy, Wm, bm, Wg, bg (f32).
// Output: concat(aln, theta, A), each (64,256,256) f32.
// ---------------------------------------------------------------------------
extern "C" void kernel_launch(void* const* d_in, const int* in_sizes, int n_in,
                              void* d_out, int out_size)
{
    const float* hx = (const float*)d_in[0];
    const float* hy = (const float*)d_in[1];
    const float* Wm = (const float*)d_in[2];
    const float* bm = (const float*)d_in[3];
    const float* Wg = (const float*)d_in[4];
    const float* bg = (const float*)d_in[5];

    float* out = (float*)d_out;
    size_t third = (size_t)out_size / 3;       // 64*256*256
    float* aln_p   = out;
    float* theta_p = out + third;
    float* A_p     = out + 2 * third;

    k_wt<<<dim3(16, 32), dim3(32, 8)>>>(Wm, Wg);
    k_mm<<<dim3(8, 256), 256>>>(0, hx, hy, bm, bg, theta_p, A_p);
    k_mm<<<dim3(4, 128), 256>>>(1, hx, hy, bm, bg, theta_p, A_p);
    k_nw<<<BATCH, 256>>>(theta_p, A_p, aln_p);
}

// round 16
// speedup vs baseline: 1.6091x; 1.0001x over previous
#include <cuda_runtime.h>
#include <cuda_bf16.h>
#include <math.h>
#include <stdint.h>

// Problem constants
#define BATCH 64
#define NSEQ  256
#define MSEQ  256
#define BIGF  1e8f

// Scratch (device globals — no runtime allocation allowed)
__device__ float  g_Z [32768u * 1024u];        // [hx;hy] @ [Wm|Wg] + bias
__device__ float  g_Wt[1024u * 512u];          // W transposed: g_Wt[n][k]
__device__ float2 g_W [(size_t)BATCH * 513 * 257];  // NW backward weights

// ===========================================================================
// Helpers
// ===========================================================================
__device__ __forceinline__ uint32_t smem_u32(const void* p) {
    uint32_t a;
    asm("{ .reg .u64 t; cvta.to.shared.u64 t, %1; cvt.u32.u64 %0, t; }"
        : "=r"(a) : "l"(p));
    return a;
}
__device__ __forceinline__ void ldm_x4(uint32_t* r, uint32_t addr) {
    asm volatile("ldmatrix.sync.aligned.m8n8.x4.shared.b16 {%0,%1,%2,%3}, [%4];"
                 : "=r"(r[0]), "=r"(r[1]), "=r"(r[2]), "=r"(r[3]) : "r"(addr));
}
__device__ __forceinline__ void mma_bf16(float* c, const uint32_t* a,
                                         const uint32_t* b) {
    asm volatile(
        "mma.sync.aligned.m16n8k16.row.col.f32.bf16.bf16.f32 "
        "{%0,%1,%2,%3}, {%4,%5,%6,%7}, {%8,%9}, {%0,%1,%2,%3};"
        : "+f"(c[0]), "+f"(c[1]), "+f"(c[2]), "+f"(c[3])
        : "r"(a[0]), "r"(a[1]), "r"(a[2]), "r"(a[3]), "r"(b[0]), "r"(b[1]));
}
// bf16x3 split: x = hi + lo (hi = bf16 rn, lo = bf16 of residual)
__device__ __forceinline__ void split_pair(float x, float y,
                                           uint32_t& hi, uint32_t& lo) {
    __nv_bfloat16 hx = __float2bfloat16(x);
    __nv_bfloat16 hy = __float2bfloat16(y);
    __nv_bfloat162 h2; h2.x = hx; h2.y = hy;
    hi = *reinterpret_cast<uint32_t*>(&h2);
    __nv_bfloat162 l2;
    l2.x = __float2bfloat16(x - __bfloat162float(hx));
    l2.y = __float2bfloat16(y - __bfloat162float(hy));
    lo = *reinterpret_cast<uint32_t*>(&l2);
}
// e^x for x <= 0, FMA-pipe polynomial (no MUFU). Degree-7 Taylor of 2^f,
// f in [0,1), exponent stitched via bits. Max rel err ~1.5e-6.
// fexp(0) == 1.0f exactly (Horner c0 = 1); x <= -87 underflows to ~0.
__device__ __forceinline__ float fexp(float x) {
    float t  = fmaxf(x * 1.442695041f, -126.0f);
    float fl = floorf(t);
    float f  = t - fl;
    float p  =            1.5252733e-5f;
    p = fmaf(p, f, 1.5403530e-4f);
    p = fmaf(p, f, 1.3333558e-3f);
    p = fmaf(p, f, 9.6181291e-3f);
    p = fmaf(p, f, 5.5504109e-2f);
    p = fmaf(p, f, 2.4022651e-1f);
    p = fmaf(p, f, 6.9314718e-1f);
    p = fmaf(p, f, 1.0f);
    int e = (int)fl;
    return p * __int_as_float((uint32_t)(e + 127) << 23);
}

// ---------------------------------------------------------------------------
// K0: transpose W into g_Wt[n][k] (n<512: Wm col n; else Wg col n-512).
// ---------------------------------------------------------------------------
__global__ void k_wt(const float* __restrict__ Wm, const float* __restrict__ Wg)
{
    __shared__ float t[32][33];
    const int bx = blockIdx.x;            // k-tile 0..15
    const int by = blockIdx.y;            // n-tile 0..31
    const float* W = (by < 16) ? Wm : Wg;
    const int nb = (by < 16 ? by : by - 16) * 32;
    for (int r = threadIdx.y; r < 32; r += 8)
        t[r][threadIdx.x] = W[(size_t)(bx * 32 + r) * 512 + nb + threadIdx.x];
    __syncthreads();
    for (int r = threadIdx.y; r < 32; r += 8)
        g_Wt[(size_t)(by * 32 + r) * 512 + bx * 32 + threadIdx.x] =
            t[threadIdx.x][r];
}

// ---------------------------------------------------------------------------
// K1: bf16x3 split-mma GEMM (base-ISA mma.sync — compute_100-compatible).
// (R15 configuration — measured-good, unchanged.)
// ---------------------------------------------------------------------------
__global__ __launch_bounds__(256) void k_mm(int mode,
    const float* __restrict__ hx, const float* __restrict__ hy,
    const float* __restrict__ bm, const float* __restrict__ bg,
    float* __restrict__ theta, float* __restrict__ Aout)
{
    __shared__ __align__(16) char sm[40960];
    const uint32_t sb = smem_u32(sm);
    const int tid = threadIdx.x, wid = tid >> 5, lane = tid & 31;

    const float *Asrc, *Bsrc, *bias = nullptr;
    size_t lda, ldb;
    int row0 = 0, n0 = 0, which = 0, batch = 0, mtile = 0, ntile = 0;
    if (mode == 0) {
        n0 = blockIdx.x * 128; row0 = blockIdx.y * 128;
        Asrc = (row0 < 16384) ? hx + (size_t)row0 * 512
                              : hy + (size_t)(row0 - 16384) * 512;
        lda = 512;
        Bsrc = g_Wt + (size_t)n0 * 512; ldb = 512;
        bias = (n0 < 512) ? bm + n0 : bg + (n0 - 512);
    } else {
        which = blockIdx.x >> 1; ntile = blockIdx.x & 1;
        batch = blockIdx.y >> 1; mtile = blockIdx.y & 1;
        Asrc = g_Z + (size_t)(batch * 256 + mtile * 128) * 1024 + which * 512;
        lda = 1024;
        Bsrc = g_Z + (size_t)(16384 + batch * 256 + ntile * 128) * 1024 + which * 512;
        ldb = 1024;
    }

    const uint32_t AHo = 0, ALo = 10240, BHo = 20480, BLo = 30720;
    const int grow = tid >> 1;
    const int gc0  = (tid & 1) * 16;

    const int wm = wid >> 1, wn = wid & 1;
    const uint32_t aoff = (uint32_t)(lane & 15) * 80 + (uint32_t)(lane >> 4) * 16;
    const uint32_t boff =
        (uint32_t)((lane & 7) + ((lane >> 4) << 3)) * 80 +
        (uint32_t)((lane >> 3) & 1) * 16;
    const uint32_t a0h = sb + AHo + (uint32_t)(wm * 32) * 80 + aoff;
    const uint32_t a1h = a0h + 16 * 80;
    const uint32_t a0l = sb + ALo + (uint32_t)(wm * 32) * 80 + aoff;
    const uint32_t a1l = a0l + 16 * 80;
    uint32_t bph[4], bpl[4];
#pragma unroll
    for (int p = 0; p < 4; p++) {
        bph[p] = sb + BHo + (uint32_t)(wn * 64 + p * 16) * 80 + boff;
        bpl[p] = sb + BLo + (uint32_t)(wn * 64 + p * 16) * 80 + boff;
    }

    float c0[8][4], c1[8][4];
#pragma unroll
    for (int n = 0; n < 8; n++)
#pragma unroll
        for (int q = 0; q < 4; q++) { c0[n][q] = 0.f; c1[n][q] = 0.f; }

    float4 pa[4], pb[4];
#pragma unroll
    for (int q = 0; q < 4; q++) {
        pa[q] = *(const float4*)(Asrc + (size_t)grow * lda + gc0 + q * 4);
        pb[q] = *(const float4*)(Bsrc + (size_t)grow * ldb + gc0 + q * 4);
    }

    for (int k0 = 0; k0 < 512; k0 += 32) {
#pragma unroll
        for (int q = 0; q < 4; q++) {
            uint32_t h0, l0, h1, l1;
            const uint32_t off = (uint32_t)grow * 80 + (uint32_t)gc0 * 2 + q * 8;
            split_pair(pa[q].x, pa[q].y, h0, l0);
            split_pair(pa[q].z, pa[q].w, h1, l1);
            *(uint2*)(sm + AHo + off) = make_uint2(h0, h1);
            *(uint2*)(sm + ALo + off) = make_uint2(l0, l1);
            split_pair(pb[q].x, pb[q].y, h0, l0);
            split_pair(pb[q].z, pb[q].w, h1, l1);
            *(uint2*)(sm + BHo + off) = make_uint2(h0, h1);
            *(uint2*)(sm + BLo + off) = make_uint2(l0, l1);
        }
        __syncthreads();
        if (k0 + 32 < 512) {
#pragma unroll
            for (int q = 0; q < 4; q++) {
                pa[q] = *(const float4*)(Asrc + (size_t)grow * lda + (k0 + 32) + gc0 + q * 4);
                pb[q] = *(const float4*)(Bsrc + (size_t)grow * ldb + (k0 + 32) + gc0 + q * 4);
            }
        }
#pragma unroll
        for (int ks = 0; ks < 2; ks++) {
            const uint32_t ko = ks * 32;
            uint32_t AH0[4], AH1[4], AL0[4], AL1[4];
            ldm_x4(AH0, a0h + ko); ldm_x4(AH1, a1h + ko);
            ldm_x4(AL0, a0l + ko); ldm_x4(AL1, a1l + ko);
            uint32_t BHf[4][4], BLf[4][4];
#pragma unroll
            for (int p = 0; p < 4; p++) {
                ldm_x4(BHf[p], bph[p] + ko);
                ldm_x4(BLf[p], bpl[p] + ko);
            }
#pragma unroll
            for (int n = 0; n < 8; n++) {
                uint32_t* bh = &BHf[n >> 1][(n & 1) * 2];
                uint32_t* bl = &BLf[n >> 1][(n & 1) * 2];
                mma_bf16(c0[n], AH0, bh);
                mma_bf16(c0[n], AH0, bl);
                mma_bf16(c0[n], AL0, bh);
                mma_bf16(c1[n], AH1, bh);
                mma_bf16(c1[n], AH1, bl);
                mma_bf16(c1[n], AL1, bh);
            }
        }
        __syncthreads();
    }

    const int g  = lane >> 2;
    const int tt = (lane & 3) * 2;
#pragma unroll
    for (int mi = 0; mi < 2; mi++) {
        float (*cc)[4] = mi ? c1 : c0;
        const int rb = wm * 32 + mi * 16 + g;
#pragma unroll
        for (int n = 0; n < 8; n++) {
            const int col = wn * 64 + n * 8 + tt;
            if (mode == 0) {
                const int row = row0 + rb;
                const float b0v = bias[col], b1v = bias[col + 1];
                *(float2*)&g_Z[(size_t)row * 1024 + n0 + col] =
                    make_float2(cc[n][0] + b0v, cc[n][1] + b1v);
                *(float2*)&g_Z[(size_t)(row + 8) * 1024 + n0 + col] =
                    make_float2(cc[n][2] + b0v, cc[n][3] + b1v);
            } else {
                float* O = which ? Aout : theta;
                const int row  = mtile * 128 + rb;
                const int ocol = ntile * 128 + col;
                const size_t base = (size_t)batch * NSEQ * MSEQ;
                float v[4];
#pragma unroll
                for (int h = 0; h < 4; h++) {
                    float x  = cc[n][h];
                    float l1 = log1pf(expf(-fabsf(x)));
                    v[h] = which ? (fminf(x, 0.f) - l1)    // log_sigmoid
                                 : (fmaxf(x, 0.f) + l1);   // softplus
                }
                *(float2*)&O[base + (size_t)row * MSEQ + ocol] =
                    make_float2(v[0], v[1]);
                *(float2*)&O[base + (size_t)(row + 8) * MSEQ + ocol] =
                    make_float2(v[2], v[3]);
            }
        }
    }
}

// float4 component select without local-array spill
__device__ __forceinline__ float f4sel(const float4& v, int sel) {
    float lo = (sel == 0) ? v.x : v.y;
    float hi = (sel == 2) ? v.z : v.w;
    return (sel < 2) ? lo : hi;
}

// ---------------------------------------------------------------------------
// K3: smooth NW forward + backward — MUFU-starved version.
// R12 profile showed k_nw bound by MUFU throughput (4 fwd + 2 bwd MUFU/cell,
// 0.5 MUFU/cyc/SM). Now: all exps via FMA-pipe fexp(); 1/S via fexp(-lnS);
// g_W stores the softmax WEIGHTS (pu, pw) so the backward needs ZERO
// transcendentals. Remaining MUFU: one __logf per forward cell.
//   u = A + R(i-1,j); w = A + C(i,j-1); m1 = max(u,w,0)
//   S = fexp(u-m1)+fexp(w-m1)+fexp(-m1)   (max term == 1 exactly, S >= 1)
//   L = m1 + __logf(S); rS = fexp(-__logf(S))
//   store (pu, pw) = (eu*rS, ew*rS);  bwd: wu=E*pu, wl=E*pw, wd=E-wu-wl
// ---------------------------------------------------------------------------
__global__ __launch_bounds__(256) void k_nw(const float* __restrict__ theta,
                                            const float* __restrict__ Aarr,
                                            float* __restrict__ aln)
{
    const int b = blockIdx.x;
    const int t = threadIdx.x;
    const float* TH = theta + (size_t)b * NSEQ * MSEQ;
    const float* AA = Aarr  + (size_t)b * NSEQ * MSEQ;
    float*       AL = aln   + (size_t)b * NSEQ * MSEQ;
    float2*      Wd = g_W   + (size_t)b * 513 * 257;

    __shared__ float Rb[2][258], Cb[2][258];
    __shared__ float Eb_[258], E1_[258], E2_[258];
    __shared__ float cu[258], cl[258], cd[258];

    const int i = t + 1;
    const float* rowT = TH + (size_t)(i - 1) * MSEQ;
    const float* rowA = AA + (size_t)(i - 1) * MSEQ;
    float*       rowL = AL + (size_t)(i - 1) * MSEQ;

    // -------- forward --------
    for (int m = t; m < 258; m += 256) { Rb[0][m] = 0.f; Cb[0][m] = 0.f; }
    if (t == 0) { Rb[0][0] = -BIGF; Cb[0][1] = -BIGF; }
    float4 tC, tN, aC, aN;
    tN = *(const float4*)rowT;
    aN = *(const float4*)rowA;
    __syncthreads();

    int s = 0;
    for (int k = 2; k <= 512; k++) {
        const int jm1 = k - i - 1;
        if (jm1 >= 0 && jm1 < MSEQ) {
            const int sel = jm1 & 3;
            if (sel == 0) {
                tC = tN; aC = aN;
                if (jm1 + 4 < MSEQ) {
                    tN = *(const float4*)(rowT + jm1 + 4);
                    aN = *(const float4*)(rowA + jm1 + 4);
                }
            }
            float th = f4sel(tC, sel);
            float a  = f4sel(aC, sel);
            float u  = a + Rb[s][i - 1];
            float w  = a + Cb[s][i];
            float m1 = fmaxf(fmaxf(u, w), 0.f);
            float eu = fexp(u - m1);
            float ew = fexp(w - m1);
            float e0 = fexp(-m1);
            float S  = eu + ew + e0;           // >= 1 exactly
            float lnS = __logf(S);
            float L   = m1 + lnS;
            float rS  = fexp(-lnS);            // 1/S, FMA-pipe
            Rb[s ^ 1][i] = th + a + (L - w);
            Cb[s ^ 1][i] = th + a + (L - u);
            Wd[(size_t)k * 257 + i] = make_float2(eu * rS, ew * rS);
        }
        if (t == 0) Rb[s ^ 1][0] = 0.f;
        if (i == k) Cb[s ^ 1][i] = 0.f;
        __syncthreads();
        s ^= 1;
    }

    // -------- backward (scatter, dist-2 prefetch, zero MUFU) --------
    float *Eb = Eb_, *E1 = E1_, *E2 = E2_;
    for (int m = t; m < 258; m += 256) {
        Eb[m] = (m == 256) ? 1.f : 0.f;
        E1[m] = 0.f; E2[m] = 0.f;
        cu[m] = 0.f; cl[m] = 0.f; cd[m] = 0.f;
    }
    float4 alB = make_float4(0.f, 0.f, 0.f, 0.f);
    float2 cur = Wd[(size_t)512 * 257 + i];
    float2 n1  = Wd[(size_t)511 * 257 + i];
    __syncthreads();

    for (int k = 512; k >= 2; k--) {
        float2 n2;
        if (k > 3) n2 = Wd[(size_t)(k - 2) * 257 + i];
        const int jm1 = k - i - 1;
        float E = Eb[i];
        float wu = 0.f, wl = 0.f, wd = 0.f;
        if (jm1 >= 0 && jm1 < MSEQ) {
            wu = E * cur.x;
            wl = E * cur.y;
            wd = E - wu - wl;
            const int sel = jm1 & 3;
            if      (sel == 3) alB.w = E;
            else if (sel == 2) alB.z = E;
            else if (sel == 1) alB.y = E;
            else               alB.x = E;
            if (sel == 0) *(float4*)(rowL + jm1) = alB;
        }
        cu[i] = wu; cl[i] = wl; cd[i] = wd;
        __syncthreads();

        for (int m = t; m < 257; m += 256) {
            E1[m] += cu[m + 1] + cl[m];
            E2[m] += cd[m + 1];
        }
        for (int m = t; m < 258; m += 256) Eb[m] = 0.f;
        __syncthreads();

        float* tE = Eb; Eb = E1; E1 = E2; E2 = tE;
        cur = n1; n1 = n2;
    }
}

// ---------------------------------------------------------------------------
// Launch. Inputs: hx, hy, Wm, bm, Wg, bg (f32).
// Output: concat(aln, theta, A), each (64,256,256) f32.
// ---------------------------------------------------------------------------
extern "C" void kernel_launch(void* const* d_in, const int* in_sizes, int n_in,
                              void* d_out, int out_size)
{
    const float* hx = (const float*)d_in[0];
    const float* hy = (const float*)d_in[1];
    const float* Wm = (const float*)d_in[2];
    const float* bm = (const float*)d_in[3];
    const float* Wg = (const float*)d_in[4];
    const float* bg = (const float*)d_in[5];

    float* out = (float*)d_out;
    size_t third = (size_t)out_size / 3;       // 64*256*256
    float* aln_p   = out;
    float* theta_p = out + third;
    float* A_p     = out + 2 * third;

    k_wt<<<dim3(16, 32), dim3(32, 8)>>>(Wm, Wg);
    k_mm<<<dim3(8, 256), 256>>>(0, hx, hy, bm, bg, theta_p, A_p);
    k_mm<<<dim3(4, 128), 256>>>(1, hx, hy, bm, bg, theta_p, A_p);
    k_nw<<<BATCH, 256>>>(theta_p, A_p, aln_p);
}